// round 15
// baseline (speedup 1.0000x reference)
#include <cuda_runtime.h>
#include <cstdint>

#define Bn 16
#define Nn 1024

// Scratch (device globals; no allocation allowed)
__device__ __align__(128) float g_S[Bn * Nn * 96];     // x @ W0 + b0    [row][ec]
__device__ __align__(128) float g_sagg[Bn * Nn * 96];  // dis[m,e]*(x@W) [row][ec] == B[k'][c] flat
__device__ __align__(128) float g_dis[Bn * Nn * 3];    // deg^-1/2       [row][e]

#define FFMA2(d, a, b) \
    asm volatile("fma.rn.f32x2 %0, %1, %2, %0;" : "+l"(d) : "l"(a), "l"(b))
#define DUP2(d, a) \
    asm volatile("mov.b64 %0, {%1,%1};" : "=l"(d) : "f"(a))
#define UNPACK2(lo, hi, v) \
    asm volatile("mov.b64 {%0,%1}, %2;" : "=f"(lo), "=f"(hi) : "l"(v))
#define CPASYNC16(dst, src) \
    asm volatile("cp.async.cg.shared.global [%0], [%1], 16;" :: "r"(dst), "l"(src))
#define CP_COMMIT() asm volatile("cp.async.commit_group;" ::: "memory")
#define CP_WAIT1()  asm volatile("cp.async.wait_group 1;" ::: "memory")
#define CP_WAIT0()  asm volatile("cp.async.wait_group 0;" ::: "memory")

__device__ __forceinline__ uint32_t sptr(const void* p) {
    return (uint32_t)__cvta_generic_to_shared(p);
}

// ---------------------------------------------------------------------------
// Kernel 1 (fused): degrees + per-row linears.  One block (128 thr) per row.
// Consecutive-48B-per-thread e-phase trick keeps the sum divergence-free.
// ---------------------------------------------------------------------------
__global__ __launch_bounds__(128) void deg_kernel(
    const float* __restrict__ adj, const float* __restrict__ x,
    const float* __restrict__ W, const float* __restrict__ W0,
    const float* __restrict__ b0)
{
    int row = blockIdx.x;                    // b*N + n
    const float4* base = (const float4*)(adj + (size_t)row * 3072);
    int t = threadIdx.x;

    __shared__ float xsh[32];
    if (t < 32) xsh[t] = x[(size_t)row * 32 + t];

    float s0 = 0.f, s1 = 0.f, s2 = 0.f;
#pragma unroll
    for (int it = 0; it < 2; it++) {
        int q0 = 3 * (t + it * 128);         // q0 % 3 == 0 always
        float4 v0 = base[q0];
        float4 v1 = base[q0 + 1];
        float4 v2 = base[q0 + 2];
        s0 += v0.x + v0.w + v1.z + v2.y;
        s1 += v0.y + v1.x + v1.w + v2.z;
        s2 += v0.z + v1.y + v2.x + v2.w;
    }
#pragma unroll
    for (int off = 16; off; off >>= 1) {
        s0 += __shfl_down_sync(0xffffffffu, s0, off);
        s1 += __shfl_down_sync(0xffffffffu, s1, off);
        s2 += __shfl_down_sync(0xffffffffu, s2, off);
    }
    __shared__ float red[4][3];
    __shared__ float dis_s[3];
    int w = t >> 5, lane = t & 31;
    if (lane == 0) { red[w][0] = s0; red[w][1] = s1; red[w][2] = s2; }
    __syncthreads();
    if (t < 3) {
        float tot = red[0][t] + red[1][t] + red[2][t] + red[3][t];
        float d = rsqrtf(fmaxf(tot, 1.0f));
        dis_s[t] = d;
        g_dis[(size_t)row * 3 + t] = d;
    }
    __syncthreads();

    if (t < 96) {
        float a = 0.f, a0 = 0.f;
#pragma unroll
        for (int k = 0; k < 32; k++) {
            float xv = xsh[k];
            a  += xv * __ldg(W  + k * 96 + t);
            a0 += xv * __ldg(W0 + k * 96 + t);
        }
        g_sagg[(size_t)row * 96 + t] = dis_s[t >> 5] * a;
        g_S[(size_t)row * 96 + t]    = a0 + __ldg(b0 + t);
    }
}

// ---------------------------------------------------------------------------
// Kernel 2: aggregation SGEMM with e-PURE warps — occupancy-shaped.
//   out[n][c] = mask * ( sum_e dis[n,e] * P_e[n][c] + sum_e S[n][ec] )
//   P_e[n][c] = sum_m adj[n][3m+e] * sagg_flat[(3m+e)*32 + c]
// Block = 192 thr (6 warps) = 32 n-rows (halved vs R14 to cut acc regs 2x and
// double the grid); warp (we = w>>1, wh = w&1) handles k' === we (mod 3) for
// its m-half; dis applied at the merge.
//   - A cp.async'd in natural [n][k'] layout; A-reads LDS.32, pad-100 rows ->
//     8 rg-lanes on distinct banks (1 phase).
//   - Thread tile 4n x 8c (lane = rg*4+cg; n = rg+8i i<4, c = cg*8..cg*8+7).
// m chunks of 32 (A 12.8KB + B 12.3KB, double-buffered) -> 50KB smem,
// 3 blocks/SM (launch_bounds 192,3), grid 512.
// Merge slots: 32 floats + 4 pad -> stride 36 (matches acc[4][4]).
// ---------------------------------------------------------------------------
#define AS_ROW   100                        // floats per n-row (96 + 4 pad)
#define AS_FL    (32 * AS_ROW)              // 3200 floats per buffer
#define BS_FL    (96 * 32)                  // 3072 floats per buffer
#define SLOT_STR 36                         // merge slot stride (32 + 4 pad)
#define SMEM_TOT ((2 * AS_FL + 2 * BS_FL) * 4)   // 50176 B

__global__ __launch_bounds__(192, 3) void agg_kernel(
    const float* __restrict__ adj,
    const int* __restrict__ mask,
    float* __restrict__ out)
{
    extern __shared__ __align__(16) float sm[];
    float* As = sm;                          // [2][32][100]
    float* Bs = sm + 2 * AS_FL;              // [2][96*32]

    int t = threadIdx.x, w = t / 32, lane = t & 31;
    int we = w >> 1, wh = w & 1;             // edge type, m-half
    int rg = lane >> 2, cg = lane & 3;       // n-octet lane, c-octet
    int b = blockIdx.y, n0 = blockIdx.x * 32;

    const float* adjb = adj + ((size_t)b * Nn + n0) * 3072;
    const float* sgb  = g_sagg + (size_t)b * Nn * 96;
    uint32_t as_addr = sptr(As), bs_addr = sptr(Bs);

    // cp.async fills: A 768 granules (4/thr), B 768 granules (4/thr)
    auto cpAB = [&](int buf, int ck) {
#pragma unroll
        for (int i = 0; i < 4; i++) {
            int q = t + 192 * i;
            int n = q / 24, seg = q % 24;
            CPASYNC16(as_addr + (uint32_t)(buf * AS_FL * 4 + n * (AS_ROW * 4) + seg * 16),
                      adjb + (size_t)n * 3072 + ck * 96 + seg * 4);
        }
#pragma unroll
        for (int i = 0; i < 4; i++) {
            int q = t + 192 * i;
            CPASYNC16(bs_addr + (uint32_t)(buf * BS_FL * 4 + q * 16),
                      sgb + (size_t)ck * 3072 + q * 4);
        }
        CP_COMMIT();
    };

    unsigned long long acc[4][4];            // [i: n=rg+8i][cpair]
#pragma unroll
    for (int i = 0; i < 4; i++)
#pragma unroll
        for (int p = 0; p < 4; p++) acc[i][p] = 0ull;

    cpAB(0, 0);
    cpAB(1, 1);

    for (int ck = 0; ck < 32; ck++) {
        if (ck < 31) { CP_WAIT1(); } else { CP_WAIT0(); }
        __syncthreads();                     // buffer ck ready for all

        const float* af = As + (ck & 1) * AS_FL + rg * AS_ROW;
        const float* bf = Bs + (ck & 1) * BS_FL + cg * 8;
#pragma unroll
        for (int j = 0; j < 16; j++) {
            const int ml = wh * 16 + j;      // m local to chunk
            const int kl = 3 * ml + we;      // k' local (e-pure)
            ulonglong2 bv0 = *(const ulonglong2*)(bf + kl * 32);
            ulonglong2 bv1 = *(const ulonglong2*)(bf + kl * 32 + 4);
#pragma unroll
            for (int i = 0; i < 4; i++) {
                float a = af[i * (8 * AS_ROW) + kl];
                unsigned long long a2;
                DUP2(a2, a);
                FFMA2(acc[i][0], a2, bv0.x);
                FFMA2(acc[i][1], a2, bv0.y);
                FFMA2(acc[i][2], a2, bv1.x);
                FFMA2(acc[i][3], a2, bv1.y);
            }
        }
        __syncthreads();                     // all reads of buffer ck done
        if (ck < 30) cpAB(ck & 1, ck + 2);
    }

    // ---- merge: 6 single-e partials, dis applied here ----
    float* slot = sm + (size_t)(w * 32 + lane) * SLOT_STR;   // 27.6 KB region
#pragma unroll
    for (int i = 0; i < 4; i++)
#pragma unroll
        for (int p = 0; p < 4; p++) {
            float lo, hi;
            UNPACK2(lo, hi, acc[i][p]);
            slot[(i * 4 + p) * 2]     = lo;
            slot[(i * 4 + p) * 2 + 1] = hi;
        }
    __syncthreads();

    for (int o = t; o < 512; o += 192) {     // 32 n x 16 c-pairs
        int n = o >> 4, cp = o & 15;
        int rg2 = n & 7, i2 = n >> 3;
        int cg2 = cp >> 2, p2 = cp & 3;
        int foff = (i2 * 4 + p2) * 2;
        size_t rown = (size_t)b * Nn + n0 + n;
        float lo = 0.f, hi = 0.f;
#pragma unroll
        for (int e = 0; e < 3; e++) {
            float d = g_dis[rown * 3 + e];
            const float* p0 = sm + (size_t)((e * 2 + 0) * 32 + rg2 * 4 + cg2) * SLOT_STR + foff;
            const float* p1 = sm + (size_t)((e * 2 + 1) * 32 + rg2 * 4 + cg2) * SLOT_STR + foff;
            lo += d * (p0[0] + p1[0]);
            hi += d * (p0[1] + p1[1]);
        }
        const float* Sp = g_S + rown * 96 + cp * 2;
        lo += Sp[0] + Sp[32] + Sp[64];
        hi += Sp[1] + Sp[33] + Sp[65];
        if (mask[rown] == 0) { lo = 0.f; hi = 0.f; }
        float2 o2; o2.x = lo; o2.y = hi;
        *(float2*)(out + rown * 32 + cp * 2) = o2;
    }
}

// ---------------------------------------------------------------------------
extern "C" void kernel_launch(void* const* d_in, const int* in_sizes, int n_in,
                              void* d_out, int out_size)
{
    const float* x    = (const float*)d_in[0];   // [16,1024,32]
    const float* adj  = (const float*)d_in[1];   // [16,1024,1024,3]
    const int*   mask = (const int*)d_in[2];     // [16,1024] bool -> int32
    const float* W    = (const float*)d_in[3];   // [32,96]
    const float* W0   = (const float*)d_in[4];   // [32,96]
    const float* b0   = (const float*)d_in[5];   // [96]
    float*       out  = (float*)d_out;           // [16,1024,32]

    (void)in_sizes; (void)n_in; (void)out_size;

    cudaFuncSetAttribute(agg_kernel, cudaFuncAttributeMaxDynamicSharedMemorySize, SMEM_TOT);

    deg_kernel<<<Bn * Nn, 128>>>(adj, x, W, W0, b0);
    agg_kernel<<<dim3(Nn / 32, Bn), 192, SMEM_TOT>>>(adj, mask, out);
}

// round 16
// speedup vs baseline: 1.7216x; 1.7216x over previous
#include <cuda_runtime.h>
#include <cuda_bf16.h>
#include <cstdint>

#define Bn 16
#define Nn 1024

// Scratch (device globals; no allocation allowed)
__device__ __align__(128) float g_S[Bn * Nn * 96];     // x@W0 + b0   [row][ec]
__device__ __align__(128) float g_dis[Bn * Nn * 3];    // deg^-1/2    [row][e]
__device__ __align__(128) __nv_bfloat16 g_adjbf[(size_t)Bn * 3 * Nn * Nn];  // [b][e][n][m]  96 MiB
__device__ __align__(128) __nv_bfloat16 g_saggbf[(size_t)Bn * 3 * Nn * 32]; // [b][e][m][c]  3 MiB

#define CPASYNC16(dst, src) \
    asm volatile("cp.async.cg.shared.global [%0], [%1], 16;" :: "r"(dst), "l"(src))
#define CP_COMMIT() asm volatile("cp.async.commit_group;" ::: "memory")
#define CP_WAIT1()  asm volatile("cp.async.wait_group 1;" ::: "memory")
#define CP_WAIT0()  asm volatile("cp.async.wait_group 0;" ::: "memory")

__device__ __forceinline__ uint32_t sptr(const void* p) {
    return (uint32_t)__cvta_generic_to_shared(p);
}
__device__ __forceinline__ uint32_t pk2(float a, float b) {
    __nv_bfloat162 h = __floats2bfloat162_rn(a, b);
    return *(uint32_t*)&h;
}

// ---------------------------------------------------------------------------
// Kernel 1 (fused): degrees + per-row linears + bf16 re-layout.
// One block (128 thr) per (b,n) row.  Each thread reads 3 consecutive float4
// (k' = 12q..12q+11, all e-phases compile-time); those 12 values are exactly
// m = 4q..4q+3 for each of the 3 edge types -> 8B bf16x4 stores into the
// deinterleaved copy g_adjbf[b][e][n][m].  Epilogue: dis, x@W/x@W0 linears,
// fp32 g_S + bf16 g_saggbf (= dis[m,e] * (x@W)).
// ---------------------------------------------------------------------------
__global__ __launch_bounds__(128) void deg_kernel(
    const float* __restrict__ adj, const float* __restrict__ x,
    const float* __restrict__ W, const float* __restrict__ W0,
    const float* __restrict__ b0)
{
    int row = blockIdx.x;                    // b*N + n
    int b = row >> 10, n = row & 1023;
    const float4* base = (const float4*)(adj + (size_t)row * 3072);
    int t = threadIdx.x;

    __shared__ float xsh[32];
    if (t < 32) xsh[t] = x[(size_t)row * 32 + t];

    float s0 = 0.f, s1 = 0.f, s2 = 0.f;
#pragma unroll
    for (int it = 0; it < 2; it++) {
        int q0 = 3 * (t + it * 128);         // q0 % 3 == 0 always
        float4 v0 = base[q0];
        float4 v1 = base[q0 + 1];
        float4 v2 = base[q0 + 2];
        // e-patterns: v0: 0,1,2,0 ; v1: 1,2,0,1 ; v2: 2,0,1,2
        s0 += v0.x + v0.w + v1.z + v2.y;
        s1 += v0.y + v1.x + v1.w + v2.z;
        s2 += v0.z + v1.y + v2.x + v2.w;

        // deinterleaved bf16 writes: m = 4t+512it .. +3 per e
        size_t mo = (size_t)(4 * t) + (size_t)it * 512;
        __nv_bfloat16* dst0 = g_adjbf + (((size_t)(b * 3 + 0) << 10 | n) << 10) + mo;
        __nv_bfloat16* dst1 = g_adjbf + (((size_t)(b * 3 + 1) << 10 | n) << 10) + mo;
        __nv_bfloat16* dst2 = g_adjbf + (((size_t)(b * 3 + 2) << 10 | n) << 10) + mo;
        uint2 u;
        u.x = pk2(v0.x, v0.w); u.y = pk2(v1.z, v2.y);
        *(uint2*)dst0 = u;
        u.x = pk2(v0.y, v1.x); u.y = pk2(v1.w, v2.z);
        *(uint2*)dst1 = u;
        u.x = pk2(v0.z, v1.y); u.y = pk2(v2.x, v2.w);
        *(uint2*)dst2 = u;
    }
#pragma unroll
    for (int off = 16; off; off >>= 1) {
        s0 += __shfl_down_sync(0xffffffffu, s0, off);
        s1 += __shfl_down_sync(0xffffffffu, s1, off);
        s2 += __shfl_down_sync(0xffffffffu, s2, off);
    }
    __shared__ float red[4][3];
    __shared__ float dis_s[3];
    int w = t >> 5, lane = t & 31;
    if (lane == 0) { red[w][0] = s0; red[w][1] = s1; red[w][2] = s2; }
    __syncthreads();
    if (t < 3) {
        float tot = red[0][t] + red[1][t] + red[2][t] + red[3][t];
        float d = rsqrtf(fmaxf(tot, 1.0f));
        dis_s[t] = d;
        g_dis[(size_t)row * 3 + t] = d;
    }
    __syncthreads();

    if (t < 96) {
        int e = t >> 5, c = t & 31;
        float a = 0.f, a0 = 0.f;
#pragma unroll
        for (int k = 0; k < 32; k++) {
            float xv = xsh[k];
            a  += xv * __ldg(W  + k * 96 + t);
            a0 += xv * __ldg(W0 + k * 96 + t);
        }
        g_S[(size_t)row * 96 + t] = a0 + __ldg(b0 + t);
        g_saggbf[(((size_t)(b * 3 + e) << 10 | n) << 5) + c] =
            __float2bfloat16(dis_s[e] * a);
    }
}

// ---------------------------------------------------------------------------
// Kernel 2: aggregation as 3 e-pure bf16 tensor GEMMs (mma.sync HMMA path).
//   P_e[n][c] = sum_m adjbf[b][e][n][m] * saggbf[b][e][m][c]   (fp32 accum)
//   out[n][c] = mask * ( sum_e dis[n,e]*P_e + sum_e S[n][e*32+c] )
// Block = 128 thr (4 warps) = 32 n-rows x 32 c.  Warp (wn = w&1, wc = w>>1)
// owns a 16n x 16c tile: per k16 step 1 ldmatrix.x4 (A) + 2 ldmatrix.x2.trans
// (B) + 2 mma.m16n8k16.  K streamed in 24 chunks of 128 (e = chunk>>3),
// cp.async double-buffered; dis folded into fp32 res at each e boundary.
// Pads: A rows 272B (k-stride banks 4r: conflict-free ldmatrix),
//       B rows 80B (banks 20k mod 32: conflict-free).
// ---------------------------------------------------------------------------
#define AS_B (32 * 272)                     // 8704 B per A buffer
#define BS_B (128 * 80)                     // 10240 B per B buffer

__global__ __launch_bounds__(128) void agg_kernel(
    const int* __restrict__ mask,
    float* __restrict__ out)
{
    __shared__ __align__(16) unsigned char As[2][AS_B];
    __shared__ __align__(16) unsigned char Bs[2][BS_B];

    int t = threadIdx.x, w = t >> 5, lane = t & 31;
    int wn = w & 1, wc = w >> 1;
    int b = blockIdx.y, n0 = blockIdx.x * 32;

    uint32_t asb = sptr(&As[0][0]), bsb = sptr(&Bs[0][0]);
    const __nv_bfloat16* adjb = g_adjbf + ((size_t)b * 3 << 20);
    const __nv_bfloat16* sgb  = g_saggbf + ((size_t)b * 3 << 15);

    auto cpAB = [&](int buf, int i) {
        int e = i >> 3, k0 = (i & 7) * 128;
        const __nv_bfloat16* Asrc = adjb + (((size_t)e << 10) + n0) * 1024 + k0;
        uint32_t ad = asb + (uint32_t)buf * AS_B;
#pragma unroll
        for (int j = 0; j < 4; j++) {
            int g = t + 128 * j;
            int row = g >> 4, seg = g & 15;
            CPASYNC16(ad + (uint32_t)(row * 272 + seg * 16),
                      Asrc + (size_t)row * 1024 + seg * 8);
        }
        const __nv_bfloat16* Bsrc = sgb + (((size_t)e << 10) + k0) * 32;
        uint32_t bd = bsb + (uint32_t)buf * BS_B;
#pragma unroll
        for (int j = 0; j < 4; j++) {
            int g = t + 128 * j;
            int kr = g >> 2, seg = g & 3;
            CPASYNC16(bd + (uint32_t)(kr * 80 + seg * 16),
                      Bsrc + (size_t)kr * 32 + seg * 8);
        }
        CP_COMMIT();
    };

    float acc[2][4], res[2][4];
#pragma unroll
    for (int f = 0; f < 2; f++)
#pragma unroll
        for (int p = 0; p < 4; p++) { acc[f][p] = 0.f; res[f][p] = 0.f; }

    int lrow = lane & 15, lhalf = lane >> 4;

    cpAB(0, 0);
    cpAB(1, 1);

    for (int i = 0; i < 24; i++) {
        if (i < 23) CP_WAIT1(); else CP_WAIT0();
        __syncthreads();

        uint32_t ab = asb + (uint32_t)((i & 1) * AS_B)
                    + (uint32_t)((wn * 16 + lrow) * 272 + lhalf * 16);
        uint32_t bb = bsb + (uint32_t)((i & 1) * BS_B)
                    + (uint32_t)(lrow * 80 + wc * 32);
#pragma unroll
        for (int kk = 0; kk < 8; kk++) {
            uint32_t a0, a1, a2, a3;
            asm volatile("ldmatrix.sync.aligned.m8n8.x4.shared.b16 {%0,%1,%2,%3}, [%4];"
                : "=r"(a0), "=r"(a1), "=r"(a2), "=r"(a3)
                : "r"(ab + (uint32_t)(kk * 32)));
#pragma unroll
            for (int f = 0; f < 2; f++) {
                uint32_t b0, b1;
                asm volatile("ldmatrix.sync.aligned.m8n8.x2.trans.shared.b16 {%0,%1}, [%2];"
                    : "=r"(b0), "=r"(b1)
                    : "r"(bb + (uint32_t)(kk * 16 * 80 + f * 16)));
                asm volatile(
                    "mma.sync.aligned.m16n8k16.row.col.f32.bf16.bf16.f32 "
                    "{%0,%1,%2,%3}, {%4,%5,%6,%7}, {%8,%9}, {%0,%1,%2,%3};"
                    : "+f"(acc[f][0]), "+f"(acc[f][1]), "+f"(acc[f][2]), "+f"(acc[f][3])
                    : "r"(a0), "r"(a1), "r"(a2), "r"(a3), "r"(b0), "r"(b1));
            }
        }
        __syncthreads();
        if (i < 22) cpAB(i & 1, i + 2);

        if ((i & 7) == 7) {                  // e boundary: fold dis, reset acc
            int e = i >> 3;
            int r0 = n0 + wn * 16 + (lane >> 2);
            float d0 = g_dis[((size_t)b * 1024 + r0) * 3 + e];
            float d1 = g_dis[((size_t)b * 1024 + r0 + 8) * 3 + e];
#pragma unroll
            for (int f = 0; f < 2; f++) {
                res[f][0] += d0 * acc[f][0];
                res[f][1] += d0 * acc[f][1];
                res[f][2] += d1 * acc[f][2];
                res[f][3] += d1 * acc[f][3];
                acc[f][0] = acc[f][1] = acc[f][2] = acc[f][3] = 0.f;
            }
        }
    }

    // epilogue: + self term, mask, store
    int r0 = n0 + wn * 16 + (lane >> 2);
#pragma unroll
    for (int h = 0; h < 2; h++) {
        int r = r0 + h * 8;
        size_t rown = (size_t)b * 1024 + r;
        int mk = mask[rown];
#pragma unroll
        for (int f = 0; f < 2; f++) {
            int c = wc * 16 + f * 8 + 2 * (lane & 3);
            const float* Sp = g_S + rown * 96 + c;
            float sx = Sp[0] + Sp[32] + Sp[64];
            float sy = Sp[1] + Sp[33] + Sp[65];
            float2 o;
            o.x = res[f][h * 2 + 0] + sx;
            o.y = res[f][h * 2 + 1] + sy;
            if (mk == 0) { o.x = 0.f; o.y = 0.f; }
            *(float2*)(out + rown * 32 + c) = o;
        }
    }
}

// ---------------------------------------------------------------------------
extern "C" void kernel_launch(void* const* d_in, const int* in_sizes, int n_in,
                              void* d_out, int out_size)
{
    const float* x    = (const float*)d_in[0];   // [16,1024,32]
    const float* adj  = (const float*)d_in[1];   // [16,1024,1024,3]
    const int*   mask = (const int*)d_in[2];     // [16,1024] bool -> int32
    const float* W    = (const float*)d_in[3];   // [32,96]
    const float* W0   = (const float*)d_in[4];   // [32,96]
    const float* b0   = (const float*)d_in[5];   // [96]
    float*       out  = (float*)d_out;           // [16,1024,32]

    (void)in_sizes; (void)n_in; (void)out_size;

    deg_kernel<<<Bn * Nn, 128>>>(adj, x, W, W0, b0);
    agg_kernel<<<dim3(Nn / 32, Bn), 128>>>(mask, out);
}